// round 11
// baseline (speedup 1.0000x reference)
#include <cuda_runtime.h>

#define B_  128
#define T_  64
#define N_  81
#define M_  128
#define G4_ 512

typedef unsigned long long ull;

__device__ __forceinline__ float frcp(float x) {
    float r; asm("rcp.approx.ftz.f32 %0, %1;" : "=f"(r) : "f"(x)); return r;
}
__device__ __forceinline__ float sigm(float x) {
    return frcp(1.0f + __expf(-x));
}
__device__ __forceinline__ float tanhe(float x) {           // exp-based, accurate
    return 2.0f * frcp(1.0f + __expf(-2.0f * x)) - 1.0f;
}
__device__ __forceinline__ float tanhap(float x) {          // HW tanh, 1 MUFU
    float r; asm("tanh.approx.f32 %0, %1;" : "=f"(r) : "f"(x)); return r;
}
__device__ __forceinline__ ull pk2(float a, float b) {
    ull r; asm("mov.b64 %0, {%1, %2};" : "=l"(r) : "f"(a), "f"(b)); return r;
}
__device__ __forceinline__ ull fma2(ull a, ull b, ull c) {
    ull d;
    asm("fma.rn.f32x2 %0, %1, %2, %3;" : "=l"(d) : "l"(a), "l"(b), "l"(c));
    return d;
}
__device__ __forceinline__ void unpk2(ull v, float& lo, float& hi) {
    asm("mov.b64 {%0, %1}, %2;" : "=f"(lo), "=f"(hi) : "l"(v));
}

// ---------------------------------------------------------------------------
// One block per (b, t-half). 512 threads, 2 blocks/SM.
// smem regions (floats):
//  HC:  hc[32][257] = 8224 (t-local rows) -> reused as Us[96][65] = 6240
//  XB:  Xst[81][34] = 2754 (gates, own t-half, transposed) -> Xs[5184] (full X)
//  C:   Ws chunk [<=41][c64][gate] <= 10496 (gates)
//       -> Wes 4096 | As 32x65 = 2080 | Ues 4096 -> LUT 5184 + AL 1296
//  Z:   z[512]; VS/UB/HS small.  Total 26832 floats = 107328 B.
// ---------------------------------------------------------------------------
#define HC_OFF    0
#define HC_PITCH  257
#define US_OFF    0
#define XB_OFF    8224
#define XST_PITCH 34
#define C_OFF     13408
#define WS_OFF    C_OFF
#define WES_OFF   C_OFF
#define AS_OFF    (C_OFF + 4096)
#define UES_OFF   (C_OFF + 6176)
#define LUT_OFF   (C_OFF + 6176)                 // after Ues is dead
#define AL_OFF    (C_OFF + 11360)
#define Z_OFF     26064
#define VS_OFF    26576
#define UB_OFF    26640
#define HS_OFF    26704
#define TOT_SMEM  (26832 * 4)                    // 107328 B

__global__ void __launch_bounds__(512, 2)
k_all(const float* __restrict__ X,   const float* __restrict__ h0,
      const float* __restrict__ s0,  const float* __restrict__ Wl,
      const float* __restrict__ Ul,  const float* __restrict__ bl,
      const float* __restrict__ Wew, const float* __restrict__ Web,
      const float* __restrict__ Uew, const float* __restrict__ Ueb,
      const float* __restrict__ vew, float* __restrict__ out) {
    extern __shared__ float sm[];
    float* hcsm = sm + HC_OFF;
    float* Xst  = sm + XB_OFF;
    float* Ws   = sm + WS_OFF;
    float* zsm  = sm + Z_OFF;
    float* vs   = sm + VS_OFF;
    float* ub   = sm + UB_OFF;
    float* hs   = sm + HS_OFF;
    int b = blockIdx.x >> 1, th = blockIdx.x & 1;
    int tid = threadIdx.x;
    int wid = tid >> 5, lane = tid & 31;
    int tbase = th * 32;                         // global t offset of this half

    // ---- prologue: Xst (own t-half, transposed), h0, vs, ub ----
    for (int idx = tid; idx < 32 * N_; idx += 512) {
        int t = idx / N_, k = idx - t * N_;
        Xst[k * XST_PITCH + t] = X[(b * T_ + tbase + t) * N_ + k];
    }
    if (tid < M_) hs[tid] = h0[b * M_ + tid];
    else if (tid < M_ + 64)       vs[tid - M_]       = vew[tid - M_];
    else if (tid < M_ + 128)      ub[tid - M_ - 64]  = Ueb[tid - M_ - 64];
    __syncthreads();

    // ---- z = h0 @ U_lstm + b_lstm (one g per thread, MLP-8) ----
    {
        const float* Up = Ul + tid;
        float a0 = bl[tid], a1 = 0.f, a2 = 0.f, a3 = 0.f;
#pragma unroll
        for (int k = 0; k < M_; k += 8) {
            float u0 = Up[(k + 0) * G4_], u1 = Up[(k + 1) * G4_];
            float u2 = Up[(k + 2) * G4_], u3 = Up[(k + 3) * G4_];
            float u4 = Up[(k + 4) * G4_], u5 = Up[(k + 5) * G4_];
            float u6 = Up[(k + 6) * G4_], u7 = Up[(k + 7) * G4_];
            a0 += hs[k + 0] * u0;  a1 += hs[k + 1] * u1;
            a2 += hs[k + 2] * u2;  a3 += hs[k + 3] * u3;
            a0 += hs[k + 4] * u4;  a1 += hs[k + 5] * u5;
            a2 += hs[k + 6] * u6;  a3 += hs[k + 7] * u7;
        }
        zsm[tid] = (a0 + a1) + (a2 + a3);
    }

    // ---- gates (own 32 t): X@W_lstm + z ; LSTM cell ; hc -> smem ----
    // warp = (t-group of 4: wid&7) x (m 32-band: wid>>3); stage = m-half;
    // W staged in k-chunks of 41/40 to fit smem.
    {
        int tg = wid & 7, ml = wid >> 3;
        for (int stage = 0; stage < 2; stage++) {
            ull acc[4][2];
#pragma unroll
            for (int g = 0; g < 4; g++)
#pragma unroll
                for (int p = 0; p < 2; p++) acc[g][p] = 0ull;

            for (int kc = 0; kc < 2; kc++) {
                int kb = kc ? 41 : 0;
                int kn = kc ? 40 : 41;
                __syncthreads();
                for (int idx = tid; idx < kn * 256; idx += 512) {
                    int k = idx >> 8, j = idx & 255;
                    int g = j >> 6, c = j & 63;
                    Ws[k * 256 + c * 4 + g] =
                        Wl[(kb + k) * G4_ + g * M_ + stage * 64 + c];
                }
                __syncthreads();
#pragma unroll 3
                for (int k = 0; k < kn; k++) {
                    const float* xr = &Xst[(kb + k) * XST_PITCH + tg * 4];
                    ull x0 = *(const ull*)(xr + 0);
                    ull x1 = *(const ull*)(xr + 2);
                    float4 w4 = *(const float4*)&Ws[k * 256 + (ml * 32 + lane) * 4];
                    ull di = pk2(w4.x, w4.x);
                    ull df = pk2(w4.y, w4.y);
                    ull dg = pk2(w4.z, w4.z);
                    ull do_ = pk2(w4.w, w4.w);
                    acc[0][0] = fma2(x0, di, acc[0][0]);
                    acc[0][1] = fma2(x1, di, acc[0][1]);
                    acc[1][0] = fma2(x0, df, acc[1][0]);
                    acc[1][1] = fma2(x1, df, acc[1][1]);
                    acc[2][0] = fma2(x0, dg, acc[2][0]);
                    acc[2][1] = fma2(x1, dg, acc[2][1]);
                    acc[3][0] = fma2(x0, do_, acc[3][0]);
                    acc[3][1] = fma2(x1, do_, acc[3][1]);
                }
            }

            int m = stage * 64 + ml * 32 + lane;
            float zi = zsm[0 * M_ + m];
            float zf = zsm[1 * M_ + m];
            float zg = zsm[2 * M_ + m];
            float zo = zsm[3 * M_ + m];
            float sv = s0[b * M_ + m];
#pragma unroll
            for (int p = 0; p < 2; p++) {
                float vi[2], vf[2], vg[2], vo[2];
                unpk2(acc[0][p], vi[0], vi[1]);
                unpk2(acc[1][p], vf[0], vf[1]);
                unpk2(acc[2][p], vg[0], vg[1]);
                unpk2(acc[3][p], vo[0], vo[1]);
#pragma unroll
                for (int hh_ = 0; hh_ < 2; hh_++) {
                    int tl = tg * 4 + 2 * p + hh_;          // t-local 0..31
                    float iv = sigm(vi[hh_] + zi);
                    float fv = sigm(vf[hh_] + zf);
                    float gv = tanhe(vg[hh_] + zg);
                    float ov = sigm(vo[hh_] + zo);
                    float cc = fv * sv + iv * gv;
                    float hv = ov * tanhe(cc);
                    hcsm[tl * HC_PITCH + m]      = hv;
                    hcsm[tl * HC_PITCH + M_ + m] = cc;
                }
            }
        }
    }

    // ---- phase A: A[tl][j] = hc[tl,:] @ We_w[:,j] + We_b[j] (own 32 t) ----
    float* As = sm + AS_OFF;
    {
        float* Wes = sm + WES_OFF;
        int r = tid >> 4;                        // 0..31 row (t-local)
        int c0 = (tid & 15) * 4;
        float acc[4];
#pragma unroll
        for (int j = 0; j < 4; j++) acc[j] = Web[c0 + j];

        for (int kc = 0; kc < 4; kc++) {
            __syncthreads();                     // Ws / prev Wes dead
            for (int idx = tid; idx < 4096; idx += 512)
                Wes[idx] = Wew[kc * 4096 + idx];
            __syncthreads();
#pragma unroll 4
            for (int k = 0; k < 64; k++) {
                float a0 = hcsm[r * HC_PITCH + kc * 64 + k];
                float4 w = *(const float4*)&Wes[k * 64 + c0];
                acc[0] += a0 * w.x; acc[1] += a0 * w.y;
                acc[2] += a0 * w.z; acc[3] += a0 * w.w;
            }
        }
        __syncthreads();                         // all hcsm reads done
#pragma unroll
        for (int j = 0; j < 4; j++)
            As[r * 65 + c0 + j] = acc[j];
    }

    // ---- phase U: U[i][k] = sum_{all t} X[b,t,i]*Ue_w[t,k] + Ue_b[k] ----
    // Xs (full X, row-major) overwrites Xst; Us overwrites hcsm.
    float* Us = sm + US_OFF;
    float* Xs = sm + XB_OFF;
    {
        float* Ues = sm + UES_OFF;
        for (int idx = tid; idx < 5184; idx += 512) Xs[idx] = X[b * 5184 + idx];
        for (int idx = tid; idx < 4096; idx += 512) Ues[idx] = Uew[idx];
        __syncthreads();

        if (tid < 336) {
            int ig = tid >> 4, kq = tid & 15, i0 = ig * 4;
            int ni = (i0 + 4 <= N_) ? 4 : (N_ - i0);
            float4 bias = *(const float4*)&ub[kq * 4];
            float4 a0 = bias, a1 = bias, a2 = bias, a3 = bias;
#pragma unroll 4
            for (int t = 0; t < T_; t++) {
                float4 u = *(const float4*)&Ues[t * 64 + kq * 4];
                const float* xr = &Xs[t * N_ + i0];
                float x0 = xr[0], x1 = xr[1], x2 = xr[2], x3 = xr[3];
                a0.x += x0 * u.x; a0.y += x0 * u.y; a0.z += x0 * u.z; a0.w += x0 * u.w;
                a1.x += x1 * u.x; a1.y += x1 * u.y; a1.z += x1 * u.z; a1.w += x1 * u.w;
                a2.x += x2 * u.x; a2.y += x2 * u.y; a2.z += x2 * u.z; a2.w += x2 * u.w;
                a3.x += x3 * u.x; a3.y += x3 * u.y; a3.z += x3 * u.z; a3.w += x3 * u.w;
            }
            float4 av[4] = {a0, a1, a2, a3};
            for (int j = 0; j < ni; j++) {
                float* up = &Us[(i0 + j) * 65 + kq * 4];
                up[0] = av[j].x; up[1] = av[j].y; up[2] = av[j].z; up[3] = av[j].w;
            }
        }
        // zero-pad rows 81..95 so lane+64 reads in phase 3 stay in-region
        for (int idx = tid; idx < (96 - N_) * 65; idx += 512)
            Us[N_ * 65 + idx] = 0.0f;
    }

    // ---- phase 3: scores + softmax + fused output streaming (own 32 t) ----
    __syncthreads();
    {
        bool v2 = (lane + 64 < N_);
        float*  alw = sm + AL_OFF + wid * 81;
        float4* lut = (float4*)(sm + LUT_OFF) + wid * 81;
        const float4* X4s = (const float4*)Xs;

        for (int tl = wid; tl < 32; tl += 16) {
            float a0 = 0.f, a1 = 0.f, a2 = 0.f;
            const float* Ap = &As[tl * 65];
            const float* U0 = &Us[lane * 65];
            const float* U1 = &Us[(lane + 32) * 65];
            const float* U2 = &Us[(lane + 64) * 65];
#pragma unroll 4
            for (int k = 0; k < 64; k++) {
                float av = Ap[k], vv = vs[k];
                a0 += vv * tanhap(av + U0[k]);
                a1 += vv * tanhap(av + U1[k]);
                a2 += vv * tanhap(av + U2[k]);
            }
            if (!v2) a2 = -1e30f;
            float mx = fmaxf(fmaxf(a0, a1), a2);
#pragma unroll
            for (int off = 16; off; off >>= 1)
                mx = fmaxf(mx, __shfl_xor_sync(0xffffffffu, mx, off));
            float e0 = __expf(a0 - mx);
            float e1 = __expf(a1 - mx);
            float e2 = __expf(a2 - mx);
            float sum = e0 + e1 + e2;
#pragma unroll
            for (int off = 16; off; off >>= 1)
                sum += __shfl_xor_sync(0xffffffffu, sum, off);
            float inv = frcp(sum);
            alw[lane]      = e0 * inv;
            alw[lane + 32] = e1 * inv;
            if (v2) alw[lane + 64] = e2 * inv;
            __syncwarp();

            // expanded float4 alpha LUT (period-81 mapping, gcd(4,81)=1)
#pragma unroll
            for (int rr = 0; rr < 3; rr++) {
                int r = lane + rr * 32;
                if (r < N_) {
                    int i0 = (4 * r) % N_;
                    int i1 = i0 + 1; if (i1 >= N_) i1 -= N_;
                    int i2 = i1 + 1; if (i2 >= N_) i2 -= N_;
                    int i3 = i2 + 1; if (i3 >= N_) i3 -= N_;
                    lut[r] = make_float4(alw[i0], alw[i1], alw[i2], alw[i3]);
                }
            }
            __syncwarp();

            float4* O = (float4*)out + (size_t)((tbase + tl) * B_ + b) * 1296;
            int r = lane % N_;
#pragma unroll 4
            for (int j = lane; j < 1296; j += 32) {
                float4 x = X4s[j];
                float4 a = lut[r];
                float4 o = make_float4(x.x * a.x, x.y * a.y, x.z * a.z, x.w * a.w);
                __stcs(&O[j], o);
                r += 32; if (r >= N_) r -= N_;
            }
            __syncwarp();
        }
    }
}

// ---------------------------------------------------------------------------
extern "C" void kernel_launch(void* const* d_in, const int* in_sizes, int n_in,
                              void* d_out, int out_size) {
    const float* X   = (const float*)d_in[0];
    const float* h0  = (const float*)d_in[1];
    const float* s0  = (const float*)d_in[2];
    const float* Wl  = (const float*)d_in[3];
    const float* Ul  = (const float*)d_in[4];
    const float* bl  = (const float*)d_in[5];
    const float* Wew = (const float*)d_in[6];
    const float* Web = (const float*)d_in[7];
    const float* Uew = (const float*)d_in[8];
    const float* Ueb = (const float*)d_in[9];
    const float* vew = (const float*)d_in[10];
    // d_in[11] = ve_b: constant pre-softmax shift -> softmax-invariant, unused.
    float* out = (float*)d_out;

    cudaFuncSetAttribute(k_all, cudaFuncAttributeMaxDynamicSharedMemorySize, TOT_SMEM);
    k_all<<<B_ * 2, 512, TOT_SMEM>>>(X, h0, s0, Wl, Ul, bl,
                                     Wew, Web, Uew, Ueb, vew, out);
    (void)in_sizes; (void)n_in; (void)out_size;
}

// round 12
// speedup vs baseline: 1.0302x; 1.0302x over previous
#include <cuda_runtime.h>

#define B_  128
#define T_  64
#define N_  81
#define M_  128
#define G4_ 512

typedef unsigned long long ull;

__device__ __forceinline__ float frcp(float x) {
    float r; asm("rcp.approx.ftz.f32 %0, %1;" : "=f"(r) : "f"(x)); return r;
}
__device__ __forceinline__ float sigm(float x) {
    return frcp(1.0f + __expf(-x));
}
__device__ __forceinline__ float tanhe(float x) {           // exp-based, accurate
    return 2.0f * frcp(1.0f + __expf(-2.0f * x)) - 1.0f;
}
__device__ __forceinline__ float tanhap(float x) {          // HW tanh, 1 MUFU
    float r; asm("tanh.approx.f32 %0, %1;" : "=f"(r) : "f"(x)); return r;
}
__device__ __forceinline__ ull pk2(float a, float b) {
    ull r; asm("mov.b64 %0, {%1, %2};" : "=l"(r) : "f"(a), "f"(b)); return r;
}
__device__ __forceinline__ ull fma2(ull a, ull b, ull c) {
    ull d;
    asm("fma.rn.f32x2 %0, %1, %2, %3;" : "=l"(d) : "l"(a), "l"(b), "l"(c));
    return d;
}
__device__ __forceinline__ void unpk2(ull v, float& lo, float& hi) {
    asm("mov.b64 {%0, %1}, %2;" : "=f"(lo), "=f"(hi) : "l"(v));
}

// ---------------------------------------------------------------------------
// One block per b, 1024 threads (32 warps), 1 block/SM. Same data plan as R10:
//  HC:  hc[64][257] = 16448 -> reused as Us[96][65] = 6240
//  XB:  Xst[81][66] = 5346 (gates, transposed) -> Xs[5184]
//  C:   Ws[81*256] = 20736 per m-half stage
//       -> As 64x65 = 4160 | {Wes 4096 / LUT 10368} | AL 2592
//  small: z[512], vs, ub, hs.  Total 43300 floats = 173200 B.
// ---------------------------------------------------------------------------
#define HC_OFF    0
#define HC_PITCH  257
#define US_OFF    0
#define XB_OFF    16448
#define XST_PITCH 66
#define C_OFF     21796
#define WS_OFF    C_OFF
#define AS_OFF    C_OFF                          // As written after last Ws use
#define WES_OFF   (C_OFF + 4160)                 // 25956 (16B aligned)
#define LUT_OFF   (C_OFF + 4160)                 // phase3 (Wes dead)
#define AL_OFF    (C_OFF + 4160 + 32 * 81 * 4)   // 36324
#define Z_OFF     42532
#define VS_OFF    43044
#define UB_OFF    43108
#define HS_OFF    43172
#define TOT_SMEM  (43300 * 4)                    // 173200 B

__global__ void __launch_bounds__(1024, 1)
k_all(const float* __restrict__ X,   const float* __restrict__ h0,
      const float* __restrict__ s0,  const float* __restrict__ Wl,
      const float* __restrict__ Ul,  const float* __restrict__ bl,
      const float* __restrict__ Wew, const float* __restrict__ Web,
      const float* __restrict__ Uew, const float* __restrict__ Ueb,
      const float* __restrict__ vew, float* __restrict__ out) {
    extern __shared__ float sm[];
    float* hcsm = sm + HC_OFF;
    float* Xst  = sm + XB_OFF;
    float* Ws   = sm + WS_OFF;
    float* zsm  = sm + Z_OFF;
    float* vs   = sm + VS_OFF;
    float* ub   = sm + UB_OFF;
    float* hs   = sm + HS_OFF;
    int b = blockIdx.x, tid = threadIdx.x;
    int wid = tid >> 5, lane = tid & 31;

    // ---- prologue: Xst (transposed X), h0, vs, ub ----
    for (int idx = tid; idx < T_ * N_; idx += 1024) {
        int t = idx / N_, k = idx - t * N_;
        Xst[k * XST_PITCH + t] = X[b * T_ * N_ + idx];
    }
    if (tid < M_) hs[tid] = h0[b * M_ + tid];
    else if (tid < M_ + 64)       vs[tid - M_]       = vew[tid - M_];
    else if (tid < M_ + 128)      ub[tid - M_ - 64]  = Ueb[tid - M_ - 64];
    __syncthreads();

    // ---- z (warps 0-15) overlapped with Ws stage-0 preload (warps 16-31) ----
    if (tid < G4_) {
        const float* Up = Ul + tid;
        float a0 = bl[tid], a1 = 0.f, a2 = 0.f, a3 = 0.f;
#pragma unroll
        for (int k = 0; k < M_; k += 8) {
            float u0 = Up[(k + 0) * G4_], u1 = Up[(k + 1) * G4_];
            float u2 = Up[(k + 2) * G4_], u3 = Up[(k + 3) * G4_];
            float u4 = Up[(k + 4) * G4_], u5 = Up[(k + 5) * G4_];
            float u6 = Up[(k + 6) * G4_], u7 = Up[(k + 7) * G4_];
            a0 += hs[k + 0] * u0;  a1 += hs[k + 1] * u1;
            a2 += hs[k + 2] * u2;  a3 += hs[k + 3] * u3;
            a0 += hs[k + 4] * u4;  a1 += hs[k + 5] * u5;
            a2 += hs[k + 6] * u6;  a3 += hs[k + 7] * u7;
        }
        zsm[tid] = (a0 + a1) + (a2 + a3);
    } else {
        for (int idx = tid - 512; idx < 81 * 256; idx += 512) {
            int k = idx >> 8, j = idx & 255;
            int g = j >> 6, c = j & 63;
            Ws[k * 256 + c * 4 + g] = Wl[k * G4_ + g * M_ + c];   // stage 0
        }
    }
    __syncthreads();

    // ---- gates: X@W_lstm + z ; LSTM cell ; hc -> smem ----
    // 32 warps = 16 t-groups (4 t) x 2 m-bands (32 cols) per m-half stage.
    {
        int tg = wid & 15, mb = wid >> 4;
        int trow = tg * 4;
        for (int stage = 0; stage < 2; stage++) {
            if (stage == 1) {
                __syncthreads();
                for (int idx = tid; idx < 81 * 256; idx += 1024) {
                    int k = idx >> 8, j = idx & 255;
                    int g = j >> 6, c = j & 63;
                    Ws[k * 256 + c * 4 + g] = Wl[k * G4_ + g * M_ + 64 + c];
                }
                __syncthreads();
            }
            ull acc[4][2];
#pragma unroll
            for (int g = 0; g < 4; g++)
#pragma unroll
                for (int p = 0; p < 2; p++) acc[g][p] = 0ull;

#pragma unroll 3
            for (int k = 0; k < 81; k++) {
                const float* xr = &Xst[k * XST_PITCH + trow];
                ull x0 = *(const ull*)(xr + 0);
                ull x1 = *(const ull*)(xr + 2);
                float4 w4 = *(const float4*)&Ws[k * 256 + (mb * 32 + lane) * 4];
                ull di = pk2(w4.x, w4.x);
                ull df = pk2(w4.y, w4.y);
                ull dg = pk2(w4.z, w4.z);
                ull do_ = pk2(w4.w, w4.w);
                acc[0][0] = fma2(x0, di, acc[0][0]);
                acc[0][1] = fma2(x1, di, acc[0][1]);
                acc[1][0] = fma2(x0, df, acc[1][0]);
                acc[1][1] = fma2(x1, df, acc[1][1]);
                acc[2][0] = fma2(x0, dg, acc[2][0]);
                acc[2][1] = fma2(x1, dg, acc[2][1]);
                acc[3][0] = fma2(x0, do_, acc[3][0]);
                acc[3][1] = fma2(x1, do_, acc[3][1]);
            }

            int m = stage * 64 + mb * 32 + lane;
            float zi = zsm[0 * M_ + m];
            float zf = zsm[1 * M_ + m];
            float zg = zsm[2 * M_ + m];
            float zo = zsm[3 * M_ + m];
            float sv = s0[b * M_ + m];
#pragma unroll
            for (int p = 0; p < 2; p++) {
                float vi[2], vf[2], vg[2], vo[2];
                unpk2(acc[0][p], vi[0], vi[1]);
                unpk2(acc[1][p], vf[0], vf[1]);
                unpk2(acc[2][p], vg[0], vg[1]);
                unpk2(acc[3][p], vo[0], vo[1]);
#pragma unroll
                for (int hh_ = 0; hh_ < 2; hh_++) {
                    int tl = trow + 2 * p + hh_;
                    float iv = sigm(vi[hh_] + zi);
                    float fv = sigm(vf[hh_] + zf);
                    float gv = tanhe(vg[hh_] + zg);
                    float ov = sigm(vo[hh_] + zo);
                    float cc = fv * sv + iv * gv;
                    float hv = ov * tanhe(cc);
                    hcsm[tl * HC_PITCH + m]      = hv;
                    hcsm[tl * HC_PITCH + M_ + m] = cc;
                }
            }
        }
    }

    // ---- phase A: A[t][j] = hc[t,:] @ We_w[:,j] + We_b[j] ----
    float* As = sm + AS_OFF;
    {
        float* Wes = sm + WES_OFF;
        int r = tid >> 4;                        // 0..63
        int c0 = (tid & 15) * 4;
        float acc[4];
#pragma unroll
        for (int j = 0; j < 4; j++) acc[j] = Web[c0 + j];

        for (int kc = 0; kc < 4; kc++) {
            __syncthreads();                     // Ws(stage1)/prev Wes dead
            for (int idx = tid; idx < 4096; idx += 1024)
                Wes[idx] = Wew[kc * 4096 + idx];
            __syncthreads();
#pragma unroll 4
            for (int k = 0; k < 64; k++) {
                float a0 = hcsm[r * HC_PITCH + kc * 64 + k];
                float4 w = *(const float4*)&Wes[k * 64 + c0];
                acc[0] += a0 * w.x; acc[1] += a0 * w.y;
                acc[2] += a0 * w.z; acc[3] += a0 * w.w;
            }
        }
        __syncthreads();                         // hcsm reads done; As region safe
#pragma unroll
        for (int j = 0; j < 4; j++)
            As[r * 65 + c0 + j] = acc[j];
    }

    // ---- phase U: U[i][k] = sum_t X[b,t,i]*Ue_w[t,k] + Ue_b[k] ----
    // Xs (row-major) overwrites Xst; Us overwrites hcsm; Ues overwrites Wes.
    float* Us = sm + US_OFF;
    float* Xs = sm + XB_OFF;
    {
        float* Ues = sm + WES_OFF;
        for (int idx = tid; idx < 5184; idx += 1024) Xs[idx] = X[b * 5184 + idx];
        for (int idx = tid; idx < 4096; idx += 1024) Ues[idx] = Uew[idx];
        __syncthreads();

        if (tid < 648) {                          // 81 i x 8 k-octets
            int i  = tid >> 3;
            int k0 = (tid & 7) * 8;
            float4 a0 = *(const float4*)&ub[k0];
            float4 a1 = *(const float4*)&ub[k0 + 4];
#pragma unroll 4
            for (int t = 0; t < T_; t++) {
                float  x  = Xs[t * N_ + i];
                float4 u0 = *(const float4*)&Ues[t * 64 + k0];
                float4 u1 = *(const float4*)&Ues[t * 64 + k0 + 4];
                a0.x += x * u0.x; a0.y += x * u0.y; a0.z += x * u0.z; a0.w += x * u0.w;
                a1.x += x * u1.x; a1.y += x * u1.y; a1.z += x * u1.z; a1.w += x * u1.w;
            }
            float* up = &Us[i * 65 + k0];
            up[0] = a0.x; up[1] = a0.y; up[2] = a0.z; up[3] = a0.w;
            up[4] = a1.x; up[5] = a1.y; up[6] = a1.z; up[7] = a1.w;
        }
        // zero-pad rows 81..95 so lane+64 reads in phase 3 stay in-region
        for (int idx = tid; idx < (96 - N_) * 65; idx += 1024)
            Us[N_ * 65 + idx] = 0.0f;
    }

    // ---- phase 3: scores + softmax + fused output streaming ----
    __syncthreads();
    {
        bool v2 = (lane + 64 < N_);
        float*  alw = sm + AL_OFF + wid * 81;
        float4* lut = (float4*)(sm + LUT_OFF) + wid * 81;
        const float4* X4s = (const float4*)Xs;

        for (int t = wid; t < T_; t += 32) {
            float a0 = 0.f, a1 = 0.f, a2 = 0.f;
            const float* Ap = &As[t * 65];
            const float* U0 = &Us[lane * 65];
            const float* U1 = &Us[(lane + 32) * 65];
            const float* U2 = &Us[(lane + 64) * 65];
#pragma unroll 4
            for (int k = 0; k < 64; k++) {
                float av = Ap[k], vv = vs[k];
                a0 += vv * tanhap(av + U0[k]);
                a1 += vv * tanhap(av + U1[k]);
                a2 += vv * tanhap(av + U2[k]);
            }
            if (!v2) a2 = -1e30f;
            float mx = fmaxf(fmaxf(a0, a1), a2);
#pragma unroll
            for (int off = 16; off; off >>= 1)
                mx = fmaxf(mx, __shfl_xor_sync(0xffffffffu, mx, off));
            float e0 = __expf(a0 - mx);
            float e1 = __expf(a1 - mx);
            float e2 = __expf(a2 - mx);
            float sum = e0 + e1 + e2;
#pragma unroll
            for (int off = 16; off; off >>= 1)
                sum += __shfl_xor_sync(0xffffffffu, sum, off);
            float inv = frcp(sum);
            alw[lane]      = e0 * inv;
            alw[lane + 32] = e1 * inv;
            if (v2) alw[lane + 64] = e2 * inv;
            __syncwarp();

            // expanded float4 alpha LUT (period-81 mapping, gcd(4,81)=1)
#pragma unroll
            for (int rr = 0; rr < 3; rr++) {
                int r = lane + rr * 32;
                if (r < N_) {
                    int i0 = (4 * r) % N_;
                    int i1 = i0 + 1; if (i1 >= N_) i1 -= N_;
                    int i2 = i1 + 1; if (i2 >= N_) i2 -= N_;
                    int i3 = i2 + 1; if (i3 >= N_) i3 -= N_;
                    lut[r] = make_float4(alw[i0], alw[i1], alw[i2], alw[i3]);
                }
            }
            __syncwarp();

            float4* O = (float4*)out + (size_t)(t * B_ + b) * 1296;
            int r = lane % N_;
#pragma unroll 4
            for (int j = lane; j < 1296; j += 32) {
                float4 x = X4s[j];
                float4 a = lut[r];
                float4 o = make_float4(x.x * a.x, x.y * a.y, x.z * a.z, x.w * a.w);
                __stcs(&O[j], o);
                r += 32; if (r >= N_) r -= N_;
            }
            __syncwarp();
        }
    }
}

// ---------------------------------------------------------------------------
extern "C" void kernel_launch(void* const* d_in, const int* in_sizes, int n_in,
                              void* d_out, int out_size) {
    const float* X   = (const float*)d_in[0];
    const float* h0  = (const float*)d_in[1];
    const float* s0  = (const float*)d_in[2];
    const float* Wl  = (const float*)d_in[3];
    const float* Ul  = (const float*)d_in[4];
    const float* bl  = (const float*)d_in[5];
    const float* Wew = (const float*)d_in[6];
    const float* Web = (const float*)d_in[7];
    const float* Uew = (const float*)d_in[8];
    const float* Ueb = (const float*)d_in[9];
    const float* vew = (const float*)d_in[10];
    // d_in[11] = ve_b: constant pre-softmax shift -> softmax-invariant, unused.
    float* out = (float*)d_out;

    cudaFuncSetAttribute(k_all, cudaFuncAttributeMaxDynamicSharedMemorySize, TOT_SMEM);
    k_all<<<B_, 1024, TOT_SMEM>>>(X, h0, s0, Wl, Ul, bl,
                                  Wew, Web, Uew, Ueb, vew, out);
    (void)in_sizes; (void)n_in; (void)out_size;
}

// round 13
// speedup vs baseline: 1.1453x; 1.1118x over previous
#include <cuda_runtime.h>

#define B_  128
#define T_  64
#define N_  81
#define M_  128
#define G4_ 512

typedef unsigned long long ull;

__device__ __forceinline__ float frcp(float x) {
    float r; asm("rcp.approx.ftz.f32 %0, %1;" : "=f"(r) : "f"(x)); return r;
}
__device__ __forceinline__ float sigm(float x) {
    return frcp(1.0f + __expf(-x));
}
__device__ __forceinline__ float tanhe(float x) {           // exp-based, accurate
    return 2.0f * frcp(1.0f + __expf(-2.0f * x)) - 1.0f;
}
__device__ __forceinline__ float tanhap(float x) {          // HW tanh, 1 MUFU
    float r; asm("tanh.approx.f32 %0, %1;" : "=f"(r) : "f"(x)); return r;
}
__device__ __forceinline__ ull pk2(float a, float b) {
    ull r; asm("mov.b64 %0, {%1, %2};" : "=l"(r) : "f"(a), "f"(b)); return r;
}
__device__ __forceinline__ ull fma2(ull a, ull b, ull c) {
    ull d;
    asm("fma.rn.f32x2 %0, %1, %2, %3;" : "=l"(d) : "l"(a), "l"(b), "l"(c));
    return d;
}
__device__ __forceinline__ void unpk2(ull v, float& lo, float& hi) {
    asm("mov.b64 {%0, %1}, %2;" : "=f"(lo), "=f"(hi) : "l"(v));
}

// ---------------------------------------------------------------------------
// One block per b, 512 threads, 1 block/SM.
// smem (floats):
//  HC  @0      : hc[64][257] = 16448      -> reused as Us[96][68] = 6528
//  XST @16448  : Xst[81][66] = 5346 (gates only, transposed)
//  XS  @21796  : Xs[5184] row-major, live prologue -> end
//  C   @26980  : gates Ws[81*256] = 20736
//                -> phase A:  As[64][68]=4352 | Wes[16384]   (= 20736 exactly)
//                -> phase U:  Ues[4096] over Wes head
//                -> phase 3:  LUT 32*81*4=10368 | AL 32*81=2592 over Wes
//  Z   @47716  : z[512];  VS @48228, UB @48292, HS @48356
//  TOT = 48484 floats = 193936 B
// ---------------------------------------------------------------------------
#define HC_OFF    0
#define HC_PITCH  257
#define US_OFF    0
#define US_PITCH  68
#define XST_OFF   16448
#define XST_PITCH 66
#define XS_OFF    21796
#define C_OFF     26980
#define WS_OFF    C_OFF
#define AS_OFF    C_OFF
#define AS_PITCH  68
#define WES_OFF   (C_OFF + 4352)
#define UES_OFF   (C_OFF + 4352)
#define LUT_OFF   (C_OFF + 4352)
#define AL_OFF    (C_OFF + 4352 + 32 * 81 * 4)
#define Z_OFF     47716
#define VS_OFF    48228
#define UB_OFF    48292
#define HS_OFF    48356
#define TOT_SMEM  (48484 * 4)

__global__ void __launch_bounds__(512, 1)
k_all(const float* __restrict__ X,   const float* __restrict__ h0,
      const float* __restrict__ s0,  const float* __restrict__ Wl,
      const float* __restrict__ Ul,  const float* __restrict__ bl,
      const float* __restrict__ Wew, const float* __restrict__ Web,
      const float* __restrict__ Uew, const float* __restrict__ Ueb,
      const float* __restrict__ vew, float* __restrict__ out) {
    extern __shared__ float sm[];
    float* hcsm = sm + HC_OFF;
    float* Xst  = sm + XST_OFF;
    float* Xs   = sm + XS_OFF;
    float* Ws   = sm + WS_OFF;
    float* zsm  = sm + Z_OFF;
    float* vs   = sm + VS_OFF;
    float* ub   = sm + UB_OFF;
    float* hs   = sm + HS_OFF;
    int b = blockIdx.x, tid = threadIdx.x;
    int wid = tid >> 5, lane = tid & 31;

    // ---- prologue: X once from global -> both layouts; h0, vs, ub ----
    for (int idx = tid; idx < T_ * N_; idx += 512) {
        int t = idx / N_, k = idx - t * N_;
        float v = X[b * T_ * N_ + idx];
        Xs[idx] = v;
        Xst[k * XST_PITCH + t] = v;
    }
    if (tid < M_) hs[tid] = h0[b * M_ + tid];
    else if (tid < M_ + 64)       vs[tid - M_]       = vew[tid - M_];
    else if (tid < M_ + 128)      ub[tid - M_ - 64]  = Ueb[tid - M_ - 64];
    __syncthreads();

    // ---- z = h0 @ U_lstm + b_lstm (one g per thread, MLP-8) ----
    {
        const float* Up = Ul + tid;
        float a0 = bl[tid], a1 = 0.f, a2 = 0.f, a3 = 0.f;
#pragma unroll
        for (int k = 0; k < M_; k += 8) {
            float u0 = Up[(k + 0) * G4_], u1 = Up[(k + 1) * G4_];
            float u2 = Up[(k + 2) * G4_], u3 = Up[(k + 3) * G4_];
            float u4 = Up[(k + 4) * G4_], u5 = Up[(k + 5) * G4_];
            float u6 = Up[(k + 6) * G4_], u7 = Up[(k + 7) * G4_];
            a0 += hs[k + 0] * u0;  a1 += hs[k + 1] * u1;
            a2 += hs[k + 2] * u2;  a3 += hs[k + 3] * u3;
            a0 += hs[k + 4] * u4;  a1 += hs[k + 5] * u5;
            a2 += hs[k + 6] * u6;  a3 += hs[k + 7] * u7;
        }
        zsm[tid] = (a0 + a1) + (a2 + a3);
    }

    // ---- gates: X@W_lstm + z ; LSTM cell ; hc -> smem (R10 structure) ----
    {
        int tg = wid & 7, ml = wid >> 3;
        for (int stage = 0; stage < 2; stage++) {
            __syncthreads();
            for (int idx = tid; idx < 81 * 256; idx += 512) {
                int k = idx >> 8, j = idx & 255;
                int g = j >> 6, c = j & 63;
                Ws[k * 256 + c * 4 + g] = Wl[k * G4_ + g * M_ + stage * 64 + c];
            }
            __syncthreads();
            int m = stage * 64 + ml * 32 + lane;
            float zi = zsm[0 * M_ + m];
            float zf = zsm[1 * M_ + m];
            float zg = zsm[2 * M_ + m];
            float zo = zsm[3 * M_ + m];
            float sv = s0[b * M_ + m];

            for (int th = 0; th < 2; th++) {
                int trow = th * 32 + tg * 4;
                ull acc[4][2];
#pragma unroll
                for (int g = 0; g < 4; g++)
#pragma unroll
                    for (int p = 0; p < 2; p++) acc[g][p] = 0ull;

#pragma unroll 3
                for (int k = 0; k < 81; k++) {
                    const float* xr = &Xst[k * XST_PITCH + trow];
                    ull x0 = *(const ull*)(xr + 0);
                    ull x1 = *(const ull*)(xr + 2);
                    float4 w4 = *(const float4*)&Ws[k * 256 + (ml * 32 + lane) * 4];
                    ull di = pk2(w4.x, w4.x);
                    ull df = pk2(w4.y, w4.y);
                    ull dg = pk2(w4.z, w4.z);
                    ull do_ = pk2(w4.w, w4.w);
                    acc[0][0] = fma2(x0, di, acc[0][0]);
                    acc[0][1] = fma2(x1, di, acc[0][1]);
                    acc[1][0] = fma2(x0, df, acc[1][0]);
                    acc[1][1] = fma2(x1, df, acc[1][1]);
                    acc[2][0] = fma2(x0, dg, acc[2][0]);
                    acc[2][1] = fma2(x1, dg, acc[2][1]);
                    acc[3][0] = fma2(x0, do_, acc[3][0]);
                    acc[3][1] = fma2(x1, do_, acc[3][1]);
                }
#pragma unroll
                for (int p = 0; p < 2; p++) {
                    float vi[2], vf[2], vg[2], vo[2];
                    unpk2(acc[0][p], vi[0], vi[1]);
                    unpk2(acc[1][p], vf[0], vf[1]);
                    unpk2(acc[2][p], vg[0], vg[1]);
                    unpk2(acc[3][p], vo[0], vo[1]);
#pragma unroll
                    for (int hh_ = 0; hh_ < 2; hh_++) {
                        int tl = trow + 2 * p + hh_;
                        float iv = sigm(vi[hh_] + zi);
                        float fv = sigm(vf[hh_] + zf);
                        float gv = tanhe(vg[hh_] + zg);
                        float ov = sigm(vo[hh_] + zo);
                        float cc = fv * sv + iv * gv;
                        float hv = ov * tanhe(cc);
                        hcsm[tl * HC_PITCH + m]      = hv;
                        hcsm[tl * HC_PITCH + M_ + m] = cc;
                    }
                }
            }
        }
    }

    // ---- phase A: single full Wes load, one pass K=256 ----
    float* As = sm + AS_OFF;
    {
        float* Wes = sm + WES_OFF;
        __syncthreads();                         // gates Ws dead
        for (int idx = tid; idx < 16384; idx += 512)
            Wes[idx] = Wew[idx];
        __syncthreads();

        int r0 = (tid >> 4) * 2;
        int c0 = (tid & 15) * 4;
        float acc[2][4];
#pragma unroll
        for (int i = 0; i < 2; i++)
#pragma unroll
            for (int j = 0; j < 4; j++) acc[i][j] = Web[c0 + j];

#pragma unroll 4
        for (int k = 0; k < 256; k++) {
            float a0 = hcsm[r0 * HC_PITCH + k];
            float a1 = hcsm[(r0 + 1) * HC_PITCH + k];
            float4 w = *(const float4*)&Wes[k * 64 + c0];
            acc[0][0] += a0 * w.x; acc[0][1] += a0 * w.y;
            acc[0][2] += a0 * w.z; acc[0][3] += a0 * w.w;
            acc[1][0] += a1 * w.x; acc[1][1] += a1 * w.y;
            acc[1][2] += a1 * w.z; acc[1][3] += a1 * w.w;
        }
        // As region (C_OFF..4352) overlaps nothing being read now
#pragma unroll
        for (int i = 0; i < 2; i++)
#pragma unroll
            for (int j = 0; j < 4; j++)
                As[(r0 + i) * AS_PITCH + c0 + j] = acc[i][j];
    }

    // ---- phase U: U[i][k] = sum_t Xs[t,i]*Ue_w[t,k] + Ue_b[k] ----
    float* Us = sm + US_OFF;
    {
        float* Ues = sm + UES_OFF;
        __syncthreads();                         // hcsm + Wes reads done
        for (int idx = tid; idx < 4096; idx += 512) Ues[idx] = Uew[idx];
        __syncthreads();

        for (int w = tid; w < 648; w += 512) {   // 81 i x 8 k-octets
            int i  = w >> 3;
            int k0 = (w & 7) * 8;
            float4 a0 = *(const float4*)&ub[k0];
            float4 a1 = *(const float4*)&ub[k0 + 4];
#pragma unroll 4
            for (int t = 0; t < T_; t++) {
                float  x  = Xs[t * N_ + i];
                float4 u0 = *(const float4*)&Ues[t * 64 + k0];
                float4 u1 = *(const float4*)&Ues[t * 64 + k0 + 4];
                a0.x += x * u0.x; a0.y += x * u0.y; a0.z += x * u0.z; a0.w += x * u0.w;
                a1.x += x * u1.x; a1.y += x * u1.y; a1.z += x * u1.z; a1.w += x * u1.w;
            }
            *(float4*)&Us[i * US_PITCH + k0]     = a0;
            *(float4*)&Us[i * US_PITCH + k0 + 4] = a1;
        }
        // zero-pad rows 81..95 so lane+64 reads stay in-region
        for (int idx = tid; idx < (96 - N_) * US_PITCH; idx += 512)
            Us[N_ * US_PITCH + idx] = 0.0f;
    }

    // ---- phase 3: paired (t, t+32) scores + softmax + fused streaming ----
    __syncthreads();
    {
        bool v2 = (lane + 64 < N_);
        const float4* vs4  = (const float4*)vs;
        const float4* As4  = (const float4*)As;
        const float4* U04  = (const float4*)&Us[lane * US_PITCH];
        const float4* U14  = (const float4*)&Us[(lane + 32) * US_PITCH];
        const float4* U24  = (const float4*)&Us[(lane + 64) * US_PITCH];
        const float4* X4s  = (const float4*)Xs;
        float4* out4 = (float4*)out;

        for (int tp = wid; tp < 32; tp += 16) {
#pragma unroll
            for (int s = 0; s < 2; s++) {
                int t = tp + s * 32;
                float a0 = 0.f, a1 = 0.f, a2 = 0.f;
                const float4* Ap4 = As4 + t * (AS_PITCH / 4);
#pragma unroll 4
                for (int k4 = 0; k4 < 16; k4++) {
                    float4 ap = Ap4[k4];
                    float4 vv = vs4[k4];
                    float4 u0 = U04[k4];
                    float4 u1 = U14[k4];
                    float4 u2 = U24[k4];
                    a0 += vv.x * tanhap(ap.x + u0.x);
                    a0 += vv.y * tanhap(ap.y + u0.y);
                    a0 += vv.z * tanhap(ap.z + u0.z);
                    a0 += vv.w * tanhap(ap.w + u0.w);
                    a1 += vv.x * tanhap(ap.x + u1.x);
                    a1 += vv.y * tanhap(ap.y + u1.y);
                    a1 += vv.z * tanhap(ap.z + u1.z);
                    a1 += vv.w * tanhap(ap.w + u1.w);
                    a2 += vv.x * tanhap(ap.x + u2.x);
                    a2 += vv.y * tanhap(ap.y + u2.y);
                    a2 += vv.z * tanhap(ap.z + u2.z);
                    a2 += vv.w * tanhap(ap.w + u2.w);
                }
                if (!v2) a2 = -1e30f;
                float mx = fmaxf(fmaxf(a0, a1), a2);
#pragma unroll
                for (int off = 16; off; off >>= 1)
                    mx = fmaxf(mx, __shfl_xor_sync(0xffffffffu, mx, off));
                float e0 = __expf(a0 - mx);
                float e1 = __expf(a1 - mx);
                float e2 = __expf(a2 - mx);
                float sum = e0 + e1 + e2;
#pragma unroll
                for (int off = 16; off; off >>= 1)
                    sum += __shfl_xor_sync(0xffffffffu, sum, off);
                float inv = frcp(sum);
                float* alw = sm + AL_OFF + (wid * 2 + s) * 81;
                alw[lane]      = e0 * inv;
                alw[lane + 32] = e1 * inv;
                if (v2) alw[lane + 64] = e2 * inv;
                __syncwarp();

                // expanded float4 alpha LUT (period-81 mapping, gcd(4,81)=1)
                float4* lut = (float4*)(sm + LUT_OFF) + (wid * 2 + s) * 81;
#pragma unroll
                for (int rr = 0; rr < 3; rr++) {
                    int r = lane + rr * 32;
                    if (r < N_) {
                        int i0 = (4 * r) % N_;
                        int i1 = i0 + 1; if (i1 >= N_) i1 -= N_;
                        int i2 = i1 + 1; if (i2 >= N_) i2 -= N_;
                        int i3 = i2 + 1; if (i3 >= N_) i3 -= N_;
                        lut[r] = make_float4(alw[i0], alw[i1], alw[i2], alw[i3]);
                    }
                }
                __syncwarp();
            }

            // fused store for the pair: X loaded once, two outputs
            const float4* lut0 = (const float4*)(sm + LUT_OFF) + (wid * 2 + 0) * 81;
            const float4* lut1 = (const float4*)(sm + LUT_OFF) + (wid * 2 + 1) * 81;
            float4* O0 = out4 + (size_t)(tp * B_ + b) * 1296;
            float4* O1 = out4 + (size_t)((tp + 32) * B_ + b) * 1296;
            int r = lane;                         // lane < 81 always
#pragma unroll 4
            for (int j = lane; j < 1296; j += 32) {
                float4 x = X4s[j];
                float4 a0 = lut0[r];
                float4 a1 = lut1[r];
                float4 o0 = make_float4(x.x * a0.x, x.y * a0.y, x.z * a0.z, x.w * a0.w);
                float4 o1 = make_float4(x.x * a1.x, x.y * a1.y, x.z * a1.z, x.w * a1.w);
                __stcs(&O0[j], o0);
                __stcs(&O1[j], o1);
                r += 32; if (r >= N_) r -= N_;
            }
            __syncwarp();
        }
    }
}

// ---------------------------------------------------------------------------
extern "C" void kernel_launch(void* const* d_in, const int* in_sizes, int n_in,
                              void* d_out, int out_size) {
    const float* X   = (const float*)d_in[0];
    const float* h0  = (const float*)d_in[1];
    const float* s0  = (const float*)d_in[2];
    const float* Wl  = (const float*)d_in[3];
    const float* Ul  = (const float*)d_in[4];
    const float* bl  = (const float*)d_in[5];
    const float* Wew = (const float*)d_in[6];
    const float* Web = (const float*)d_in[7];
    const float* Uew = (const float*)d_in[8];
    const float* Ueb = (const float*)d_in[9];
    const float* vew = (const float*)d_in[10];
    // d_in[11] = ve_b: constant pre-softmax shift -> softmax-invariant, unused.
    float* out = (float*)d_out;

    cudaFuncSetAttribute(k_all, cudaFuncAttributeMaxDynamicSharedMemorySize, TOT_SMEM);
    k_all<<<B_, 512, TOT_SMEM>>>(X, h0, s0, Wl, Ul, bl,
                                 Wew, Web, Uew, Ueb, vew, out);
    (void)in_sizes; (void)n_in; (void)out_size;
}

// round 14
// speedup vs baseline: 1.1582x; 1.0113x over previous
#include <cuda_runtime.h>

#define B_  128
#define T_  64
#define N_  81
#define M_  128
#define G4_ 512

typedef unsigned long long ull;

__device__ __forceinline__ float frcp(float x) {
    float r; asm("rcp.approx.ftz.f32 %0, %1;" : "=f"(r) : "f"(x)); return r;
}
__device__ __forceinline__ float sigm(float x) {
    return frcp(1.0f + __expf(-x));
}
__device__ __forceinline__ float tanhe(float x) {           // exp-based, accurate
    return 2.0f * frcp(1.0f + __expf(-2.0f * x)) - 1.0f;
}
__device__ __forceinline__ float tanhap(float x) {          // HW tanh, 1 MUFU
    float r; asm("tanh.approx.f32 %0, %1;" : "=f"(r) : "f"(x)); return r;
}
__device__ __forceinline__ ull pk2(float a, float b) {
    ull r; asm("mov.b64 %0, {%1, %2};" : "=l"(r) : "f"(a), "f"(b)); return r;
}
__device__ __forceinline__ ull fma2(ull a, ull b, ull c) {
    ull d;
    asm("fma.rn.f32x2 %0, %1, %2, %3;" : "=l"(d) : "l"(a), "l"(b), "l"(c));
    return d;
}
__device__ __forceinline__ void unpk2(ull v, float& lo, float& hi) {
    asm("mov.b64 {%0, %1}, %2;" : "=f"(lo), "=f"(hi) : "l"(v));
}

// ---------------------------------------------------------------------------
// One block per b, 512 threads, 1 block/SM. R10 structure + f32x2 A/U phases.
// smem (floats):
//  HC  @0     : hc[64][257] = 16448  -> reused as Us[96][65] = 6240
//  XST @16448 : Xst[81][66] = 5346 (gates only, transposed)
//  XS  @21796 : Xs[5184] row-major, live prologue -> end
//  C   @26980 : gates Ws[81*256] = 20736
//               -> phase A:  As[64][65]=4160 @26980 | Wes[16384] @31140
//               -> phase U:  Ues[4096] @31140 (over Wes)
//               -> phase 3:  LUT 16*81*4=5184 @31140 | AL 16*81 @36324
//  Z  @47716: z[512]; VS @48228; UB @48292; HS @48356.  TOT 48484 fl = 193936 B
// ---------------------------------------------------------------------------
#define HC_OFF    0
#define HC_PITCH  257
#define US_OFF    0
#define US_PITCH  65
#define XST_OFF   16448
#define XST_PITCH 66
#define XS_OFF    21796
#define C_OFF     26980
#define WS_OFF    C_OFF
#define AS_OFF    C_OFF
#define AS_PITCH  65
#define WES_OFF   (C_OFF + 4160)                 // 31140 (16B aligned)
#define UES_OFF   (C_OFF + 4160)
#define LUT_OFF   (C_OFF + 4160)
#define AL_OFF    (C_OFF + 4160 + 16 * 81 * 4)   // 36324
#define Z_OFF     47716
#define VS_OFF    48228
#define UB_OFF    48292
#define HS_OFF    48356
#define TOT_SMEM  (48484 * 4)

__global__ void __launch_bounds__(512, 1)
k_all(const float* __restrict__ X,   const float* __restrict__ h0,
      const float* __restrict__ s0,  const float* __restrict__ Wl,
      const float* __restrict__ Ul,  const float* __restrict__ bl,
      const float* __restrict__ Wew, const float* __restrict__ Web,
      const float* __restrict__ Uew, const float* __restrict__ Ueb,
      const float* __restrict__ vew, float* __restrict__ out) {
    extern __shared__ float sm[];
    float* hcsm = sm + HC_OFF;
    float* Xst  = sm + XST_OFF;
    float* Xs   = sm + XS_OFF;
    float* Ws   = sm + WS_OFF;
    float* zsm  = sm + Z_OFF;
    float* vs   = sm + VS_OFF;
    float* ub   = sm + UB_OFF;
    float* hs   = sm + HS_OFF;
    int b = blockIdx.x, tid = threadIdx.x;
    int wid = tid >> 5, lane = tid & 31;

    // ---- prologue: X once from global -> both layouts; h0, vs, ub ----
    for (int idx = tid; idx < T_ * N_; idx += 512) {
        int t = idx / N_, k = idx - t * N_;
        float v = X[b * T_ * N_ + idx];
        Xs[idx] = v;
        Xst[k * XST_PITCH + t] = v;
    }
    if (tid < M_) hs[tid] = h0[b * M_ + tid];
    else if (tid < M_ + 64)       vs[tid - M_]       = vew[tid - M_];
    else if (tid < M_ + 128)      ub[tid - M_ - 64]  = Ueb[tid - M_ - 64];
    __syncthreads();

    // ---- z = h0 @ U_lstm + b_lstm (per-thread; overlaps stage-0 Ws staging) ----
    {
        const float* Up = Ul + tid;
        float a0 = bl[tid], a1 = 0.f, a2 = 0.f, a3 = 0.f;
#pragma unroll
        for (int k = 0; k < M_; k += 8) {
            float u0 = Up[(k + 0) * G4_], u1 = Up[(k + 1) * G4_];
            float u2 = Up[(k + 2) * G4_], u3 = Up[(k + 3) * G4_];
            float u4 = Up[(k + 4) * G4_], u5 = Up[(k + 5) * G4_];
            float u6 = Up[(k + 6) * G4_], u7 = Up[(k + 7) * G4_];
            a0 += hs[k + 0] * u0;  a1 += hs[k + 1] * u1;
            a2 += hs[k + 2] * u2;  a3 += hs[k + 3] * u3;
            a0 += hs[k + 4] * u4;  a1 += hs[k + 5] * u5;
            a2 += hs[k + 6] * u6;  a3 += hs[k + 7] * u7;
        }
        zsm[tid] = (a0 + a1) + (a2 + a3);
    }

    // ---- gates: X@W_lstm + z ; LSTM cell ; hc -> smem ----
    {
        int tg = wid & 7, ml = wid >> 3;
        for (int stage = 0; stage < 2; stage++) {
            if (stage == 1) __syncthreads();     // stage-0: no barrier (Ws fresh)
            for (int idx = tid; idx < 81 * 256; idx += 512) {
                int k = idx >> 8, j = idx & 255;
                int g = j >> 6, c = j & 63;
                Ws[k * 256 + c * 4 + g] = Wl[k * G4_ + g * M_ + stage * 64 + c];
            }
            __syncthreads();                     // Ws + all zsm published
            int m = stage * 64 + ml * 32 + lane;
            float zi = zsm[0 * M_ + m];
            float zf = zsm[1 * M_ + m];
            float zg = zsm[2 * M_ + m];
            float zo = zsm[3 * M_ + m];
            float sv = s0[b * M_ + m];

            for (int th = 0; th < 2; th++) {
                int trow = th * 32 + tg * 4;
                ull acc[4][2];
#pragma unroll
                for (int g = 0; g < 4; g++)
#pragma unroll
                    for (int p = 0; p < 2; p++) acc[g][p] = 0ull;

#pragma unroll 3
                for (int k = 0; k < 81; k++) {
                    const float* xr = &Xst[k * XST_PITCH + trow];
                    ull x0 = *(const ull*)(xr + 0);
                    ull x1 = *(const ull*)(xr + 2);
                    float4 w4 = *(const float4*)&Ws[k * 256 + (ml * 32 + lane) * 4];
                    ull di = pk2(w4.x, w4.x);
                    ull df = pk2(w4.y, w4.y);
                    ull dg = pk2(w4.z, w4.z);
                    ull do_ = pk2(w4.w, w4.w);
                    acc[0][0] = fma2(x0, di, acc[0][0]);
                    acc[0][1] = fma2(x1, di, acc[0][1]);
                    acc[1][0] = fma2(x0, df, acc[1][0]);
                    acc[1][1] = fma2(x1, df, acc[1][1]);
                    acc[2][0] = fma2(x0, dg, acc[2][0]);
                    acc[2][1] = fma2(x1, dg, acc[2][1]);
                    acc[3][0] = fma2(x0, do_, acc[3][0]);
                    acc[3][1] = fma2(x1, do_, acc[3][1]);
                }
#pragma unroll
                for (int p = 0; p < 2; p++) {
                    float vi[2], vf[2], vg[2], vo[2];
                    unpk2(acc[0][p], vi[0], vi[1]);
                    unpk2(acc[1][p], vf[0], vf[1]);
                    unpk2(acc[2][p], vg[0], vg[1]);
                    unpk2(acc[3][p], vo[0], vo[1]);
#pragma unroll
                    for (int hh_ = 0; hh_ < 2; hh_++) {
                        int tl = trow + 2 * p + hh_;
                        float iv = sigm(vi[hh_] + zi);
                        float fv = sigm(vf[hh_] + zf);
                        float gv = tanhe(vg[hh_] + zg);
                        float ov = sigm(vo[hh_] + zo);
                        float cc = fv * sv + iv * gv;
                        float hv = ov * tanhe(cc);
                        hcsm[tl * HC_PITCH + m]      = hv;
                        hcsm[tl * HC_PITCH + M_ + m] = cc;
                    }
                }
            }
        }
    }

    // ---- phase A: f32x2 column-pairs, single full Wes load ----
    float* As = sm + AS_OFF;
    {
        float* Wes = sm + WES_OFF;
        __syncthreads();                         // gates done; Ws dead
        for (int idx = tid; idx < 16384; idx += 512)
            Wes[idx] = Wew[idx];
        __syncthreads();

        int r0 = (tid >> 4) * 2;                 // 2 t-rows
        int c0 = (tid & 15) * 4;                 // 4 cols = 2 col-pairs
        ull acc[2][2];
#pragma unroll
        for (int j2 = 0; j2 < 2; j2++) {
            ull wb = *(const ull*)&((const float*)Web)[c0 + 2 * j2]; // Web 8B-aligned pairs
            acc[0][j2] = wb;
            acc[1][j2] = wb;
        }
#pragma unroll 4
        for (int k = 0; k < 256; k++) {
            float a0 = hcsm[r0 * HC_PITCH + k];
            float a1 = hcsm[(r0 + 1) * HC_PITCH + k];
            ull xa0 = pk2(a0, a0);
            ull xa1 = pk2(a1, a1);
            ulonglong2 w = *(const ulonglong2*)&Wes[k * 64 + c0];  // (c0,c0+1),(c0+2,c0+3)
            acc[0][0] = fma2(xa0, w.x, acc[0][0]);
            acc[0][1] = fma2(xa0, w.y, acc[0][1]);
            acc[1][0] = fma2(xa1, w.x, acc[1][0]);
            acc[1][1] = fma2(xa1, w.y, acc[1][1]);
        }
        // As @C_OFF overlaps dead Ws only; hcsm untouched
#pragma unroll
        for (int i = 0; i < 2; i++)
#pragma unroll
            for (int j2 = 0; j2 < 2; j2++) {
                float lo, hi;
                unpk2(acc[i][j2], lo, hi);
                As[(r0 + i) * AS_PITCH + c0 + 2 * j2]     = lo;
                As[(r0 + i) * AS_PITCH + c0 + 2 * j2 + 1] = hi;
            }
    }

    // ---- phase U (f32x2): U[i][k] = sum_t Xs[t,i]*Ue_w[t,k] + Ue_b[k] ----
    float* Us = sm + US_OFF;
    {
        float* Ues = sm + UES_OFF;
        __syncthreads();                         // hcsm + Wes reads done
        for (int idx = tid; idx < 4096; idx += 512) Ues[idx] = Uew[idx];
        __syncthreads();

        for (int w = tid; w < 648; w += 512) {   // 81 i x 8 k-octets
            int i  = w >> 3;
            int k0 = (w & 7) * 8;
            ull a0 = pk2(ub[k0 + 0], ub[k0 + 1]);
            ull a1 = pk2(ub[k0 + 2], ub[k0 + 3]);
            ull a2 = pk2(ub[k0 + 4], ub[k0 + 5]);
            ull a3 = pk2(ub[k0 + 6], ub[k0 + 7]);
#pragma unroll 4
            for (int t = 0; t < T_; t++) {
                float x = Xs[t * N_ + i];
                ull xx = pk2(x, x);
                ulonglong2 u0 = *(const ulonglong2*)&Ues[t * 64 + k0];
                ulonglong2 u1 = *(const ulonglong2*)&Ues[t * 64 + k0 + 4];
                a0 = fma2(xx, u0.x, a0);
                a1 = fma2(xx, u0.y, a1);
                a2 = fma2(xx, u1.x, a2);
                a3 = fma2(xx, u1.y, a3);
            }
            float* up = &Us[i * US_PITCH + k0];
            unpk2(a0, up[0], up[1]);
            unpk2(a1, up[2], up[3]);
            unpk2(a2, up[4], up[5]);
            unpk2(a3, up[6], up[7]);
        }
        // zero-pad rows 81..95 so lane+64 reads stay in-region
        for (int idx = tid; idx < (96 - N_) * US_PITCH; idx += 512)
            Us[N_ * US_PITCH + idx] = 0.0f;
    }

    // ---- phase 3: scores + softmax + fused output streaming (R10 form) ----
    __syncthreads();
    {
        bool v2 = (lane + 64 < N_);
        float*  alw = sm + AL_OFF + wid * 81;
        float4* lut = (float4*)(sm + LUT_OFF) + wid * 81;
        const float4* X4s = (const float4*)Xs;

        for (int t = wid; t < T_; t += 16) {
            float a0 = 0.f, a1 = 0.f, a2 = 0.f;
            const float* Ap = &As[t * AS_PITCH];
            const float* U0 = &Us[lane * US_PITCH];
            const float* U1 = &Us[(lane + 32) * US_PITCH];
            const float* U2 = &Us[(lane + 64) * US_PITCH];
#pragma unroll 4
            for (int k = 0; k < 64; k++) {
                float av = Ap[k], vv = vs[k];
                a0 += vv * tanhap(av + U0[k]);
                a1 += vv * tanhap(av + U1[k]);
                a2 += vv * tanhap(av + U2[k]);
            }
            if (!v2) a2 = -1e30f;
            float mx = fmaxf(fmaxf(a0, a1), a2);
#pragma unroll
            for (int off = 16; off; off >>= 1)
                mx = fmaxf(mx, __shfl_xor_sync(0xffffffffu, mx, off));
            float e0 = __expf(a0 - mx);
            float e1 = __expf(a1 - mx);
            float e2 = __expf(a2 - mx);
            float sum = e0 + e1 + e2;
#pragma unroll
            for (int off = 16; off; off >>= 1)
                sum += __shfl_xor_sync(0xffffffffu, sum, off);
            float inv = frcp(sum);
            alw[lane]      = e0 * inv;
            alw[lane + 32] = e1 * inv;
            if (v2) alw[lane + 64] = e2 * inv;
            __syncwarp();

            // expanded float4 alpha LUT (period-81 mapping, gcd(4,81)=1)
#pragma unroll
            for (int rr = 0; rr < 3; rr++) {
                int r = lane + rr * 32;
                if (r < N_) {
                    int i0 = (4 * r) % N_;
                    int i1 = i0 + 1; if (i1 >= N_) i1 -= N_;
                    int i2 = i1 + 1; if (i2 >= N_) i2 -= N_;
                    int i3 = i2 + 1; if (i3 >= N_) i3 -= N_;
                    lut[r] = make_float4(alw[i0], alw[i1], alw[i2], alw[i3]);
                }
            }
            __syncwarp();

            float4* O = (float4*)out + (size_t)(t * B_ + b) * 1296;
            int r = lane;
#pragma unroll 4
            for (int j = lane; j < 1296; j += 32) {
                float4 x = X4s[j];
                float4 a = lut[r];
                float4 o = make_float4(x.x * a.x, x.y * a.y, x.z * a.z, x.w * a.w);
                __stcs(&O[j], o);
                r += 32; if (r >= N_) r -= N_;
            }
            __syncwarp();
        }
    }
}

// ---------------------------------------------------------------------------
extern "C" void kernel_launch(void* const* d_in, const int* in_sizes, int n_in,
                              void* d_out, int out_size) {
    const float* X   = (const float*)d_in[0];
    const float* h0  = (const float*)d_in[1];
    const float* s0  = (const float*)d_in[2];
    const float* Wl  = (const float*)d_in[3];
    const float* Ul  = (const float*)d_in[4];
    const float* bl  = (const float*)d_in[5];
    const float* Wew = (const float*)d_in[6];
    const float* Web = (const float*)d_in[7];
    const float* Uew = (const float*)d_in[8];
    const float* Ueb = (const float*)d_in[9];
    const float* vew = (const float*)d_in[10];
    // d_in[11] = ve_b: constant pre-softmax shift -> softmax-invariant, unused.
    float* out = (float*)d_out;

    cudaFuncSetAttribute(k_all, cudaFuncAttributeMaxDynamicSharedMemorySize, TOT_SMEM);
    k_all<<<B_, 512, TOT_SMEM>>>(X, h0, s0, Wl, Ul, bl,
                                 Wew, Web, Uew, Ueb, vew, out);
    (void)in_sizes; (void)n_in; (void)out_size;
}